// round 8
// baseline (speedup 1.0000x reference)
#include <cuda_runtime.h>
#include <math.h>

#define BN 8192
#define NN 100000
#define DD 8
#define KK 32
#define CC 100
#define TOTAL (BN + NN)
#define NTILES ((TOTAL + 127) / 128)   // 846
#define GRID_MLP 296                   // 2 blocks/SM persistent

#define KT4 4     // k-tiles of 32 covering K=100 (pad 128)
#define MT2 7     // m-tiles of 16 covering M=100 (pad 112)
#define MT3 2     // m-tiles of 16 covering M=30  (pad 32)

// ---- smem layout (bytes) ----
#define SM_W2FH 0          // W2 hi frags: 4*7*128 u32 = 14336
#define SM_W2FL 14336
#define SM_W3FH 28672      // W3 hi frags: 4*2*128 u32 = 4096
#define SM_W3FL 32768
#define SM_ACTH 36864      // activations hi int8: 128 pts * 144 B
#define SM_ACTL 55296
#define SM_MISC 73728      // floats: W1[200] b1[100] b2[100] b3[32] W4[60] b4[2] red[8]@504
#define SMEM_TOTAL 75776

#define ASTR 144           // act byte stride per point: 36 words -> 4g+t banks, conflict-free

// Feature scratch: [0..BN) queries, [BN..TOTAL) nodes, (x,y) pairs.
__device__ float g_feat[TOTAL * 2];

__device__ __forceinline__ void imma32(int (&c)[4], const uint4& a, unsigned b0, unsigned b1) {
    asm("mma.sync.aligned.m16n8k32.row.col.s32.s8.s8.s32 "
        "{%0,%1,%2,%3}, {%4,%5,%6,%7}, {%8,%9}, {%0,%1,%2,%3};"
        : "+r"(c[0]), "+r"(c[1]), "+r"(c[2]), "+r"(c[3])
        : "r"(a.x), "r"(a.y), "r"(a.z), "r"(a.w), "r"(b0), "r"(b1));
}

// split 15-bit integer into hi/lo int8 (hi*128 + lo == wi exactly, |lo| <= 64)
__device__ __forceinline__ void q15(int wi, int& hi, int& lo) {
    hi = (wi + 64) >> 7;
    lo = wi - (hi << 7);
}

__global__ __launch_bounds__(256, 2)
void mlp_kernel(const float* __restrict__ x, const float* __restrict__ nd,
                const float* __restrict__ W1, const float* __restrict__ b1,
                const float* __restrict__ W2, const float* __restrict__ b2,
                const float* __restrict__ W3, const float* __restrict__ b3,
                const float* __restrict__ W4, const float* __restrict__ b4)
{
    extern __shared__ char sm[];
    float* mf  = (float*)(sm + SM_MISC);
    float* red = mf + 504;
    const uint4* W2FH4 = (const uint4*)(sm + SM_W2FH);
    const uint4* W2FL4 = (const uint4*)(sm + SM_W2FL);
    const uint4* W3FH4 = (const uint4*)(sm + SM_W3FH);
    const uint4* W3FL4 = (const uint4*)(sm + SM_W3FL);
    signed char* actH = (signed char*)(sm + SM_ACTH);
    signed char* actL = (signed char*)(sm + SM_ACTL);

    const int tid = threadIdx.x;
    const int lane = tid & 31, warp = tid >> 5;
    const int g = lane >> 2, t = lane & 3;
    const int n0 = warp * 16;              // warp owns 16 points (2 n-tiles of 8)

    // ================= phase 0: weight max, quantize+pack frags, params =================
    float mw2 = 0.f, mw3 = 0.f;
    for (int i = tid; i < 10000; i += 256) mw2 = fmaxf(mw2, fabsf(W2[i]));
    for (int i = tid; i < 3000; i += 256)  mw3 = fmaxf(mw3, fabsf(W3[i]));
    #pragma unroll
    for (int o = 16; o > 0; o >>= 1) {
        mw2 = fmaxf(mw2, __shfl_xor_sync(0xffffffffu, mw2, o));
        mw3 = fmaxf(mw3, __shfl_xor_sync(0xffffffffu, mw3, o));
    }
    if (lane == 0) { red[warp] = mw2; }
    __syncthreads();
    float m2 = red[0];
    #pragma unroll
    for (int i = 1; i < 8; i++) m2 = fmaxf(m2, red[i]);
    __syncthreads();
    if (lane == 0) { red[warp] = mw3; }
    __syncthreads();
    float m3 = red[0];
    #pragma unroll
    for (int i = 1; i < 8; i++) m3 = fmaxf(m3, red[i]);
    m2 = fmaxf(m2, 1e-20f); m3 = fmaxf(m3, 1e-20f);
    const float sw2 = m2 * (1.f / 16256.f), iw2 = 16256.f / m2;
    const float sw3 = m3 * (1.f / 16256.f), iw3 = 16256.f / m3;

    // pack W2 fragments (m16n8k32 A layout): u32 idx -> (kt,mt,lane,r)
    for (int idx = tid; idx < 3584 + 1024; idx += 256) {
        const bool is3 = idx >= 3584;
        const int id = is3 ? idx - 3584 : idx;
        const int r = id & 3, ln = (id >> 2) & 31, q = id >> 7;
        const int nmt = is3 ? MT3 : MT2;
        const int mt = q % nmt, kt = q / nmt;
        const int row = mt * 16 + (ln >> 2) + (r & 1) * 8;
        const int kb = kt * 32 + (r >> 1) * 16 + (ln & 3) * 4;
        const int rmax = is3 ? 30 : 100;
        const float* W = is3 ? W3 : W2;
        const float inv = is3 ? iw3 : iw2;
        unsigned hp = 0, lp = 0;
        #pragma unroll
        for (int b = 0; b < 4; b++) {
            const int k = kb + b;
            float w = (row < rmax && k < 100) ? W[row * 100 + k] : 0.f;
            int hi, lo;
            q15(__float2int_rn(w * inv), hi, lo);
            hp |= (hi & 255u) << (8 * b);
            lp |= (lo & 255u) << (8 * b);
        }
        if (is3) { ((unsigned*)(sm + SM_W3FH))[id] = hp; ((unsigned*)(sm + SM_W3FL))[id] = lp; }
        else     { ((unsigned*)(sm + SM_W2FH))[id] = hp; ((unsigned*)(sm + SM_W2FL))[id] = lp; }
    }
    // small params
    for (int i = tid; i < 200; i += 256) mf[i] = W1[i];
    if (tid < 100) { mf[200 + tid] = b1[tid]; mf[300 + tid] = b2[tid]; }
    if (tid < 32)  mf[400 + tid] = (tid < 30) ? b3[tid] : 0.f;
    if (tid < 60)  mf[432 + tid] = W4[tid];
    if (tid < 2)   mf[492 + tid] = b4[tid];
    // zero act pad bytes k in [100,144) once (never overwritten: writes are k<100 only)
    for (int i = tid; i < 128 * 11; i += 256) {
        const int p = i / 11, w = i % 11;
        *(unsigned*)(actH + p * ASTR + 100 + 4 * w) = 0u;
        *(unsigned*)(actL + p * ASTR + 100 + 4 * w) = 0u;
    }
    __syncthreads();

    // ================= tile loop =================
    for (int tile = blockIdx.x; tile < NTILES; tile += GRID_MLP) {
        const int pbase = tile * 128;

        // ---- layer 1: 2 -> 100, ReLU, per-tile quantize to int8 hi/lo ----
        {
            const int p = tid & 127, half = tid >> 7;
            const int pg = pbase + p;
            float px = 0.f, py = 0.f;
            if (pg < TOTAL) {
                const float2 v = (pg < BN) ? ((const float2*)x)[pg]
                                           : ((const float2*)nd)[pg - BN];
                px = v.x; py = v.y;
            }
            const int j0 = half * 50;
            float h1v[50];
            float lm = 0.f;
            #pragma unroll 10
            for (int j = 0; j < 50; j++) {
                float v = fmaf(mf[2 * (j0 + j)], px,
                          fmaf(mf[2 * (j0 + j) + 1], py, mf[200 + j0 + j]));
                v = fmaxf(v, 0.f);
                h1v[j] = v;
                lm = fmaxf(lm, v);
            }
            #pragma unroll
            for (int o = 16; o > 0; o >>= 1) lm = fmaxf(lm, __shfl_xor_sync(0xffffffffu, lm, o));
            if (lane == 0) red[warp] = lm;
            __syncthreads();
            float m1 = red[0];
            #pragma unroll
            for (int i = 1; i < 8; i++) m1 = fmaxf(m1, red[i]);
            m1 = fmaxf(m1, 1e-20f);
            const float inv1 = 16256.f / m1;
            red[504 - 504] = red[0];  // no-op keep
            // stash sa1 via register:每thread identical
            const float sa1 = m1 * (1.f / 16256.f);
            signed char* aH = actH + p * ASTR + j0;
            signed char* aL = actL + p * ASTR + j0;
            #pragma unroll 10
            for (int j = 0; j < 50; j++) {
                int hi, lo;
                q15(__float2int_rn(h1v[j] * inv1), hi, lo);
                aH[j] = (signed char)hi;
                aL[j] = (signed char)lo;
            }
            // carry scA to layer 2 through shared slot (identical across threads anyway)
            if (tid == 0) red[1] = sa1 * sw2;
        }
        __syncthreads();
        const float scA = red[1];

        // ---- layer 2: 100 -> 100 via int8 2-level IMMA ----
        unsigned bH[KT4][2][2], bL[KT4][2][2];
        #pragma unroll
        for (int kt = 0; kt < KT4; kt++)
            #pragma unroll
            for (int nt = 0; nt < 2; nt++) {
                const int off = (n0 + nt * 8 + g) * ASTR + kt * 32 + 4 * t;
                #pragma unroll
                for (int j = 0; j < 2; j++) {
                    bH[kt][nt][j] = *(const unsigned*)(actH + off + j * 16);
                    bL[kt][nt][j] = *(const unsigned*)(actL + off + j * 16);
                }
            }
        float h2v[MT2][2][4];
        {
            const float cHH = 16384.f * scA, cX = 128.f * scA;
            #pragma unroll
            for (int mt = 0; mt < MT2; mt++) {
                int hh[2][4] = {{0,0,0,0},{0,0,0,0}};
                int xx[2][4] = {{0,0,0,0},{0,0,0,0}};
                #pragma unroll
                for (int kt = 0; kt < KT4; kt++) {
                    const uint4 aH = W2FH4[(kt * MT2 + mt) * 32 + lane];
                    const uint4 aL = W2FL4[(kt * MT2 + mt) * 32 + lane];
                    #pragma unroll
                    for (int nt = 0; nt < 2; nt++) {
                        imma32(hh[nt], aH, bH[kt][nt][0], bH[kt][nt][1]);
                        imma32(xx[nt], aH, bL[kt][nt][0], bL[kt][nt][1]);
                        imma32(xx[nt], aL, bH[kt][nt][0], bH[kt][nt][1]);
                    }
                }
                #pragma unroll
                for (int nt = 0; nt < 2; nt++)
                    #pragma unroll
                    for (int r = 0; r < 4; r++) {
                        const int row = mt * 16 + g + (r >> 1) * 8;
                        const float bias = (row < 100) ? mf[300 + row] : 0.f;
                        float f = fmaf((float)hh[nt][r], cHH,
                                  fmaf((float)xx[nt][r], cX, bias));
                        if (row >= 100) f = 0.f;
                        h2v[mt][nt][r] = fmaxf(f, 0.f);
                    }
            }
        }
        // per-tile max of h2, then quantize + store over act
        {
            float lm = 0.f;
            #pragma unroll
            for (int mt = 0; mt < MT2; mt++)
                #pragma unroll
                for (int nt = 0; nt < 2; nt++)
                    #pragma unroll
                    for (int r = 0; r < 4; r++) lm = fmaxf(lm, h2v[mt][nt][r]);
            #pragma unroll
            for (int o = 16; o > 0; o >>= 1) lm = fmaxf(lm, __shfl_xor_sync(0xffffffffu, lm, o));
            if (lane == 0) red[warp] = lm;
            __syncthreads();   // also: all act(h1) reads done before overwrite
            float m2t = red[0];
            #pragma unroll
            for (int i = 1; i < 8; i++) m2t = fmaxf(m2t, red[i]);
            m2t = fmaxf(m2t, 1e-20f);
            const float inv2 = 16256.f / m2t;
            if (tid == 0) red[1] = (m2t * (1.f / 16256.f)) * sw3;   // scB for layer 3
            #pragma unroll
            for (int mt = 0; mt < MT2; mt++)
                #pragma unroll
                for (int nt = 0; nt < 2; nt++)
                    #pragma unroll
                    for (int r = 0; r < 4; r++) {
                        const int row = mt * 16 + g + (r >> 1) * 8;
                        if (row < 100) {
                            const int pt = n0 + nt * 8 + 2 * t + (r & 1);
                            int hi, lo;
                            q15(__float2int_rn(h2v[mt][nt][r] * inv2), hi, lo);
                            actH[pt * ASTR + row] = (signed char)hi;
                            actL[pt * ASTR + row] = (signed char)lo;
                        }
                    }
        }
        __syncthreads();
        const float scB = red[1];

        // ---- layer 3: 100 -> 30 via int8 2-level IMMA ----
        float D[MT3][2][4];
        {
            #pragma unroll
            for (int kt = 0; kt < KT4; kt++)
                #pragma unroll
                for (int nt = 0; nt < 2; nt++) {
                    const int off = (n0 + nt * 8 + g) * ASTR + kt * 32 + 4 * t;
                    #pragma unroll
                    for (int j = 0; j < 2; j++) {
                        bH[kt][nt][j] = *(const unsigned*)(actH + off + j * 16);
                        bL[kt][nt][j] = *(const unsigned*)(actL + off + j * 16);
                    }
                }
            const float cHH = 16384.f * scB, cX = 128.f * scB;
            #pragma unroll
            for (int mt = 0; mt < MT3; mt++) {
                int hh[2][4] = {{0,0,0,0},{0,0,0,0}};
                int xx[2][4] = {{0,0,0,0},{0,0,0,0}};
                #pragma unroll
                for (int kt = 0; kt < KT4; kt++) {
                    const uint4 aH = W3FH4[(kt * MT3 + mt) * 32 + lane];
                    const uint4 aL = W3FL4[(kt * MT3 + mt) * 32 + lane];
                    #pragma unroll
                    for (int nt = 0; nt < 2; nt++) {
                        imma32(hh[nt], aH, bH[kt][nt][0], bH[kt][nt][1]);
                        imma32(xx[nt], aH, bL[kt][nt][0], bL[kt][nt][1]);
                        imma32(xx[nt], aL, bH[kt][nt][0], bH[kt][nt][1]);
                    }
                }
                #pragma unroll
                for (int nt = 0; nt < 2; nt++)
                    #pragma unroll
                    for (int r = 0; r < 4; r++) {
                        const int row = mt * 16 + g + (r >> 1) * 8;   // < 32
                        float f = fmaf((float)hh[nt][r], cHH,
                                  fmaf((float)xx[nt][r], cX, mf[400 + row]));
                        D[mt][nt][r] = fmaxf(f, 0.f);                 // rows>=30: 0+0 -> 0
                    }
            }
        }

        // ---- layer 4: 30 -> 2 from D fragments, warp shuffle reduce ----
        {
            float acc[2][2][2];   // [nt][col01][out01]
            #pragma unroll
            for (int nt = 0; nt < 2; nt++)
                #pragma unroll
                for (int c2 = 0; c2 < 2; c2++) { acc[nt][c2][0] = 0.f; acc[nt][c2][1] = 0.f; }
            #pragma unroll
            for (int mt = 0; mt < MT3; mt++)
                #pragma unroll
                for (int half = 0; half < 2; half++) {
                    const int row = mt * 16 + g + half * 8;
                    const float w0 = (row < 30) ? mf[432 + row] : 0.f;
                    const float w1 = (row < 30) ? mf[462 + row] : 0.f;
                    #pragma unroll
                    for (int nt = 0; nt < 2; nt++) {
                        const float h0 = D[mt][nt][2 * half + 0];
                        const float h1 = D[mt][nt][2 * half + 1];
                        acc[nt][0][0] = fmaf(w0, h0, acc[nt][0][0]);
                        acc[nt][0][1] = fmaf(w1, h0, acc[nt][0][1]);
                        acc[nt][1][0] = fmaf(w0, h1, acc[nt][1][0]);
                        acc[nt][1][1] = fmaf(w1, h1, acc[nt][1][1]);
                    }
                }
            #pragma unroll
            for (int o = 4; o <= 16; o <<= 1)
                #pragma unroll
                for (int nt = 0; nt < 2; nt++)
                    #pragma unroll
                    for (int c2 = 0; c2 < 2; c2++) {
                        acc[nt][c2][0] += __shfl_xor_sync(0xffffffffu, acc[nt][c2][0], o);
                        acc[nt][c2][1] += __shfl_xor_sync(0xffffffffu, acc[nt][c2][1], o);
                    }
            if (g == 0) {
                #pragma unroll
                for (int nt = 0; nt < 2; nt++)
                    #pragma unroll
                    for (int c2 = 0; c2 < 2; c2++) {
                        const int pg = pbase + n0 + nt * 8 + 2 * t + c2;
                        if (pg < TOTAL)
                            ((float2*)g_feat)[pg] = make_float2(acc[nt][c2][0] + mf[492],
                                                                acc[nt][c2][1] + mf[493]);
                    }
            }
        }
        __syncthreads();   // act reads (layer3) complete before next tile's layer1 writes
    }
}

// ---------------- routing kernel: one block per query b ----------------
__global__ __launch_bounds__(256)
void route_kernel(const int* __restrict__ nbr_idx, const int* __restrict__ labels,
                  float* __restrict__ out)
{
    __shared__ float p_s[CC];
    __shared__ float terms[DD - 1];

    const int b = blockIdx.x;
    const int tid = threadIdx.x;
    const int d = tid >> 5, lane = tid & 31;

    if (tid < CC) p_s[tid] = 0.f;
    __syncthreads();

    const float2 q = ((const float2*)g_feat)[b];
    const int idx = nbr_idx[b * (DD * KK) + tid];
    const float2 g = ((const float2*)g_feat)[BN + idx];

    const float dx = g.x - q.x + 1e-6f;
    const float dy = g.y - q.y + 1e-6f;
    const float neg = -sqrtf(fmaf(dx, dx, dy * dy));

    float m = neg;
    #pragma unroll
    for (int o = 16; o > 0; o >>= 1) m = fmaxf(m, __shfl_xor_sync(0xffffffffu, m, o));
    const float e = __expf(neg - m);
    float s = e;
    #pragma unroll
    for (int o = 16; o > 0; o >>= 1) s += __shfl_xor_sync(0xffffffffu, s, o);

    if (d < DD - 1) {
        if (lane == 0) terms[d] = __logf(__fdividef(1.0f, s) + 1e-4f);
    } else {
        const int c = labels[idx];
        atomicAdd(&p_s[c], __fdividef(e, s));
    }
    __syncthreads();

    if (tid < CC) {
        float tsum = terms[0] + terms[1] + terms[2] + terms[3] + terms[4] + terms[5] + terms[6];
        out[(long)b * CC + tid] = __logf(p_s[tid] + 1e-4f) + tsum;
    }
}

extern "C" void kernel_launch(void* const* d_in, const int* in_sizes, int n_in,
                              void* d_out, int out_size)
{
    const float* x      = (const float*)d_in[0];
    const float* nd     = (const float*)d_in[1];
    const float* W1     = (const float*)d_in[2];
    const float* b1     = (const float*)d_in[3];
    const float* W2     = (const float*)d_in[4];
    const float* b2     = (const float*)d_in[5];
    const float* W3     = (const float*)d_in[6];
    const float* b3     = (const float*)d_in[7];
    const float* W4     = (const float*)d_in[8];
    const float* b4     = (const float*)d_in[9];
    const int*   labels = (const int*)d_in[10];
    const int*   nbr    = (const int*)d_in[11];
    float* out = (float*)d_out;

    cudaFuncSetAttribute(mlp_kernel, cudaFuncAttributeMaxDynamicSharedMemorySize, SMEM_TOTAL);

    mlp_kernel<<<GRID_MLP, 256, SMEM_TOTAL>>>(x, nd, W1, b1, W2, b2, W3, b3, W4, b4);
    route_kernel<<<BN, 256>>>(nbr, labels, out);
}